// round 8
// baseline (speedup 1.0000x reference)
#include <cuda_runtime.h>
#include <cuda_bf16.h>
#include <cstdint>

#define THREADS 256
#define NTILES  4096
#define GRID    148

// ---- smem layout (bytes) ----
#define OFF_RING 0u          // 3 x 16384 : per chunk [hi 8K][lo 8K], A[128m][32k]
#define OFF_W1   49152u      // hi 64K + lo 64K : [128 d][256 k], 512B rows
#define OFF_W2   180224u     // hi 8K + lo 8K   : [32 n][128 k], 256B rows
#define OFF_PS   196608u     // 2 x 16384 fp32 partial sums [32 n][128 m]
#define OFF_B1   229376u
#define OFF_B2   229888u
#define SMEM_TOTAL 230016u

// bf16 z in [b][y][x][ch] layout (channel-contiguous), hi and lo parts
static __device__ __align__(16) __nv_bfloat16 g_zh[8 * 256 * 256 * 32];
static __device__ __align__(16) __nv_bfloat16 g_zl[8 * 256 * 256 * 32];

__device__ __forceinline__ uint32_t smem_u32(const void* p) {
    uint32_t a;
    asm("{ .reg .u64 t; cvta.to.shared.u64 t, %1; cvt.u32.u64 %0, t; }"
        : "=r"(a) : "l"(p));
    return a;
}
__device__ __forceinline__ void ldsm4(uint32_t r[4], uint32_t addr) {
    asm volatile("ldmatrix.sync.aligned.m8n8.x4.shared.b16 {%0,%1,%2,%3}, [%4];"
                 : "=r"(r[0]), "=r"(r[1]), "=r"(r[2]), "=r"(r[3]) : "r"(addr));
}
__device__ __forceinline__ void mma16816(float c[4], const uint32_t a[4],
                                         uint32_t b0, uint32_t b1) {
    asm volatile("mma.sync.aligned.m16n8k16.row.col.f32.bf16.bf16.f32 "
                 "{%0,%1,%2,%3}, {%4,%5,%6,%7}, {%8,%9}, {%0,%1,%2,%3};"
                 : "+f"(c[0]), "+f"(c[1]), "+f"(c[2]), "+f"(c[3])
                 : "r"(a[0]), "r"(a[1]), "r"(a[2]), "r"(a[3]), "r"(b0), "r"(b1));
}
__device__ __forceinline__ uint32_t packsplit(float h0, float h1, uint32_t& lo) {
    __nv_bfloat162 th = __floats2bfloat162_rn(h0, h1);
    __nv_bfloat162 tl = __floats2bfloat162_rn(h0 - __bfloat162float(th.x),
                                              h1 - __bfloat162float(th.y));
    lo = *(uint32_t*)&tl;
    return *(uint32_t*)&th;
}
__device__ __forceinline__ void cp16(uint32_t dst, const void* src, bool ok) {
    asm volatile("cp.async.ca.shared.global [%0], [%1], 16, %2;"
                 :: "r"(dst), "l"(src), "r"(ok ? 16 : 0));
}
// A ring buffer swizzle: row stride 64B (32 bf16), granule XOR (row>>1)&3
__device__ __forceinline__ uint32_t swzA32(int m, int k) {
    return (uint32_t)(m * 64 + ((((k >> 3) ^ ((m >> 1) & 3)) & 3) << 4) + (k & 7) * 2);
}
__device__ __forceinline__ uint32_t swzW1(int d, int k) {   // 512B rows
    return (uint32_t)(d * 512 + (((k >> 3) ^ (d & 7)) << 4) + (k & 7) * 2);
}
__device__ __forceinline__ uint32_t swzW2(int r, int k) {   // 256B rows
    return (uint32_t)(r * 256 + (((k >> 3) ^ (r & 7)) << 4) + (k & 7) * 2);
}

// ---------------- pre-pass: fp32 z -> split bf16, channel-contiguous ----------------
__global__ __launch_bounds__(256)
void zconv(const float* __restrict__ z) {
    const int y = blockIdx.x, b = blockIdx.y, x = threadIdx.x;
    const float* src = z + (((size_t)b * 32) * 256 + y) * 256 + x;
    float v[32];
    #pragma unroll
    for (int ch = 0; ch < 32; ++ch) v[ch] = src[(size_t)ch * 65536];
    uint32_t hi[16], lo[16];
    #pragma unroll
    for (int i = 0; i < 16; ++i) hi[i] = packsplit(v[2 * i], v[2 * i + 1], lo[i]);
    size_t o = (((size_t)b * 256 + y) * 256 + x) * 32;
    uint4* dh = (uint4*)(g_zh + o);
    uint4* dl = (uint4*)(g_zl + o);
    #pragma unroll
    for (int i = 0; i < 4; ++i) {
        dh[i] = make_uint4(hi[4*i], hi[4*i+1], hi[4*i+2], hi[4*i+3]);
        dl[i] = make_uint4(lo[4*i], lo[4*i+1], lo[4*i+2], lo[4*i+3]);
    }
}

// ---------------- main kernel ----------------
__global__ __launch_bounds__(THREADS, 1)
void lp_mma(const float* __restrict__ W1, const float* __restrict__ b1,
            const float* __restrict__ W2, const float* __restrict__ b2,
            float* __restrict__ out)
{
    extern __shared__ __align__(16) char smem[];
    const uint32_t sb = smem_u32(smem);
    const int tid  = threadIdx.x;
    const int w    = tid >> 5;
    const int lane = tid & 31;

    // ---------- one-time weight staging ----------
    for (int idx = tid; idx < 128 * 256; idx += THREADS) {
        int d = idx >> 8, k = idx & 255;
        int q = k >> 5, ch = k & 31;
        int p = q + (q >= 4);                 // skip center tap
        float v = W1[d * 288 + ch * 9 + p];
        uint32_t lo, hi = packsplit(v, 0.0f, lo);
        uint32_t off = swzW1(d, k);
        *(__nv_bfloat16*)(smem + OFF_W1 + off)          = *(__nv_bfloat16*)&hi;
        *(__nv_bfloat16*)(smem + OFF_W1 + 65536u + off) = *(__nv_bfloat16*)&lo;
    }
    for (int idx = tid; idx < 32 * 128; idx += THREADS) {
        int n = idx >> 7, k = idx & 127;
        float v = W2[n * 128 + k];
        uint32_t lo, hi = packsplit(v, 0.0f, lo);
        uint32_t off = swzW2(n, k);
        *(__nv_bfloat16*)(smem + OFF_W2 + off)         = *(__nv_bfloat16*)&hi;
        *(__nv_bfloat16*)(smem + OFF_W2 + 8192u + off) = *(__nv_bfloat16*)&lo;
    }
    if (tid < 128) ((float*)(smem + OFF_B1))[tid] = b1[tid];
    if (tid < 32)  ((float*)(smem + OFF_B2))[tid] = b2[tid];
    __syncthreads();

    // ---------- warp tiling / lane addressing ----------
    const int mw = w & 3;                 // M slice (32 rows)
    const int nw = w >> 2;                // N slice (64 cols)
    const int arow  = lane & 15;
    const int kselA = lane >> 4;
    const int brow  = ((lane >> 4) << 3) + (lane & 7);
    const int kselB = (lane >> 3) & 1;
    const int xorA  = (arow >> 1) & 3;
    const int xorB  = brow & 7;

    uint32_t rowA1[2];
    #pragma unroll
    for (int mi = 0; mi < 2; ++mi)
        rowA1[mi] = (uint32_t)((mw * 32 + mi * 16 + arow) * 64);
    uint32_t rowB1[4];
    #pragma unroll
    for (int jq = 0; jq < 4; ++jq)
        rowB1[jq] = (uint32_t)((nw * 64 + jq * 16 + brow) * 512);
    uint32_t rowB2[2] = { (uint32_t)(brow * 256), (uint32_t)((16 + brow) * 256) };

    const int spx   = tid & 127;          // staging pixel
    const int shalf = tid >> 7;           // 16-ch half

    const float* b1s = (const float*)(smem + OFF_B1);
    const float* b2s = (const float*)(smem + OFF_B2);

    // ---------- cp.async chunk issue (chunk = 1 tap x 32 ch) ----------
    auto issue = [&](int t, int c, int buf) {
        int x0 = (t & 1) * 128, y = (t >> 1) & 255, b = t >> 9;
        int p  = c + (c >= 4);
        int di = p / 3, dj = p - di * 3;
        int yy = y + di - 1, xx = x0 + spx + dj - 1;
        bool ok = (t < NTILES) && ((unsigned)yy < 256u) && ((unsigned)xx < 256u);
        size_t o = ok ? ((((size_t)b * 256 + yy) * 256 + xx) * 32 + shalf * 16) : 0;
        const __nv_bfloat16* sh = g_zh + o;
        const __nv_bfloat16* sl = g_zl + o;
        uint32_t base = sb + OFF_RING + (uint32_t)buf * 16384u;
        uint32_t d0 = base + swzA32(spx, shalf * 16);
        uint32_t d1 = base + swzA32(spx, shalf * 16 + 8);
        cp16(d0, sh, ok);           cp16(d1, sh + 8, ok);
        cp16(d0 + 8192u, sl, ok);   cp16(d1 + 8192u, sl + 8, ok);
        asm volatile("cp.async.commit_group;");
    };

    int ibuf = 1, cbuf = 0;
    issue(blockIdx.x, 0, 0);      // prologue

    for (int t = blockIdx.x; t < NTILES; t += GRID) {
        const int x0 = (t & 1) * 128;
        const int y  = (t >> 1) & 255;
        const int b  = t >> 9;

        float C[2][8][4];
        #pragma unroll
        for (int mi = 0; mi < 2; ++mi)
            #pragma unroll
            for (int jo = 0; jo < 8; ++jo)
                #pragma unroll
                for (int r = 0; r < 4; ++r) C[mi][jo][r] = 0.0f;

        // ============ layer 1: 8 chunks of K=32, cp.async ring ============
        #pragma unroll 1
        for (int c = 0; c < 8; ++c) {
            if (c < 7) issue(t, c + 1, ibuf);
            else       issue(t + GRID, 0, ibuf);
            ibuf = (ibuf + 1) % 3;
            asm volatile("cp.async.wait_group 1;");
            __syncthreads();

            const uint32_t Ab = sb + OFF_RING + (uint32_t)cbuf * 16384u;
            cbuf = (cbuf + 1) % 3;
            const uint32_t Bh = sb + OFF_W1;
            const uint32_t Bl = sb + OFF_W1 + 65536u;
            #pragma unroll
            for (int s = 0; s < 2; ++s) {
                const uint32_t koA = (uint32_t)((((2 * s + kselA) ^ xorA) & 3) << 4);
                const uint32_t koB = (uint32_t)(((c * 4 + 2 * s + kselB) ^ xorB) << 4);
                uint32_t ah[2][4], al[2][4], bfr[4][4];
                #pragma unroll
                for (int mi = 0; mi < 2; ++mi) ldsm4(ah[mi], Ab + rowA1[mi] + koA);
                #pragma unroll
                for (int jq = 0; jq < 4; ++jq) ldsm4(bfr[jq], Bh + rowB1[jq] + koB);
                #pragma unroll
                for (int mi = 0; mi < 2; ++mi)
                    #pragma unroll
                    for (int jo = 0; jo < 8; ++jo)
                        mma16816(C[mi][jo], ah[mi],
                                 bfr[jo >> 1][(jo & 1) * 2], bfr[jo >> 1][(jo & 1) * 2 + 1]);
                #pragma unroll
                for (int mi = 0; mi < 2; ++mi) ldsm4(al[mi], Ab + 8192u + rowA1[mi] + koA);
                #pragma unroll
                for (int mi = 0; mi < 2; ++mi)
                    #pragma unroll
                    for (int jo = 0; jo < 8; ++jo)
                        mma16816(C[mi][jo], al[mi],
                                 bfr[jo >> 1][(jo & 1) * 2], bfr[jo >> 1][(jo & 1) * 2 + 1]);
                #pragma unroll
                for (int jq = 0; jq < 4; ++jq) ldsm4(bfr[jq], Bl + rowB1[jq] + koB);
                #pragma unroll
                for (int mi = 0; mi < 2; ++mi)
                    #pragma unroll
                    for (int jo = 0; jo < 8; ++jo)
                        mma16816(C[mi][jo], ah[mi],
                                 bfr[jo >> 1][(jo & 1) * 2], bfr[jo >> 1][(jo & 1) * 2 + 1]);
            }
        }

        // ============ epilogue 1 in registers: C -> layer-2 A fragments ============
        uint32_t a2h[2][4][4], a2l[2][4][4];
        {
            const int c2l = (lane & 3) * 2;
            #pragma unroll
            for (int mi = 0; mi < 2; ++mi) {
                #pragma unroll
                for (int kc = 0; kc < 4; ++kc) {
                    int n0 = nw * 64 + kc * 16 + c2l;
                    float bA = b1s[n0], bB = b1s[n0 + 1];
                    float h0 = fmaxf(C[mi][2*kc][0] + bA, 0.0f);
                    float h1 = fmaxf(C[mi][2*kc][1] + bB, 0.0f);
                    float h2 = fmaxf(C[mi][2*kc][2] + bA, 0.0f);
                    float h3 = fmaxf(C[mi][2*kc][3] + bB, 0.0f);
                    a2h[mi][kc][0] = packsplit(h0, h1, a2l[mi][kc][0]);
                    a2h[mi][kc][1] = packsplit(h2, h3, a2l[mi][kc][1]);
                    float bC = b1s[n0 + 8], bD = b1s[n0 + 9];
                    float g0 = fmaxf(C[mi][2*kc+1][0] + bC, 0.0f);
                    float g1 = fmaxf(C[mi][2*kc+1][1] + bD, 0.0f);
                    float g2 = fmaxf(C[mi][2*kc+1][2] + bC, 0.0f);
                    float g3 = fmaxf(C[mi][2*kc+1][3] + bD, 0.0f);
                    a2h[mi][kc][2] = packsplit(g0, g1, a2l[mi][kc][2]);
                    a2h[mi][kc][3] = packsplit(g2, g3, a2l[mi][kc][3]);
                }
            }
        }

        // ============ layer 2: split-K (K=64 per warp-group), N=32 ============
        float C2[2][4][4];
        #pragma unroll
        for (int mi = 0; mi < 2; ++mi)
            #pragma unroll
            for (int jo = 0; jo < 4; ++jo)
                #pragma unroll
                for (int r = 0; r < 4; ++r) C2[mi][jo][r] = 0.0f;

        #pragma unroll
        for (int ps = 0; ps < 3; ++ps) {
            const uint32_t Bb = sb + OFF_W2 + (ps == 2 ? 8192u : 0u);
            #pragma unroll
            for (int kc = 0; kc < 4; ++kc) {
                // B k-granule must match this warp-group's hidden slice:
                // absolute k = nw*64 + kc*16  ->  granule nw*8 + 2*kc (+kselB)
                const uint32_t koB = (uint32_t)(((nw * 8 + 2 * kc + kselB) ^ xorB) << 4);
                uint32_t bfr[2][4];
                #pragma unroll
                for (int jq = 0; jq < 2; ++jq) ldsm4(bfr[jq], Bb + rowB2[jq] + koB);
                #pragma unroll
                for (int mi = 0; mi < 2; ++mi) {
                    const uint32_t* A = (ps == 1) ? a2l[mi][kc] : a2h[mi][kc];
                    #pragma unroll
                    for (int jo = 0; jo < 4; ++jo)
                        mma16816(C2[mi][jo], A,
                                 bfr[jo >> 1][(jo & 1) * 2], bfr[jo >> 1][(jo & 1) * 2 + 1]);
                }
            }
        }

        // ---- split-K partials to smem ----
        {
            float* ps = (float*)(smem + OFF_PS + (uint32_t)nw * 16384u);
            const int r0 = lane >> 2, c2l = (lane & 3) * 2;
            #pragma unroll
            for (int mi = 0; mi < 2; ++mi) {
                int m = mw * 32 + mi * 16 + r0;
                #pragma unroll
                for (int jo = 0; jo < 4; ++jo) {
                    int n = jo * 8 + c2l;
                    ps[n * 128 + m]           = C2[mi][jo][0];
                    ps[(n + 1) * 128 + m]     = C2[mi][jo][1];
                    ps[n * 128 + m + 8]       = C2[mi][jo][2];
                    ps[(n + 1) * 128 + m + 8] = C2[mi][jo][3];
                }
            }
        }
        __syncthreads();

        // ---- reduce + bias + store (coalesced float4) ----
        {
            const int n  = tid >> 3;
            const int m0 = (tid & 7) * 16;
            const float* p0 = (const float*)(smem + OFF_PS) + n * 128 + m0;
            const float* p1 = (const float*)(smem + OFF_PS + 16384u) + n * 128 + m0;
            const float bz = b2s[n];
            float* po = out + ((size_t)(b * 32 + n)) * 65536 + y * 256 + x0 + m0;
            #pragma unroll
            for (int i = 0; i < 4; ++i) {
                float4 u = ((const float4*)p0)[i];
                float4 v = ((const float4*)p1)[i];
                ((float4*)po)[i] = make_float4(u.x + v.x + bz, u.y + v.y + bz,
                                               u.z + v.z + bz, u.w + v.w + bz);
            }
        }
        __syncthreads();   // PS consumed before next tile overwrites
    }
}

extern "C" void kernel_launch(void* const* d_in, const int* in_sizes, int n_in,
                              void* d_out, int out_size) {
    const float* z  = (const float*)d_in[0];
    const float* W1 = (const float*)d_in[1];
    const float* b1 = (const float*)d_in[2];
    const float* W2 = (const float*)d_in[3];
    const float* b2 = (const float*)d_in[4];
    float* out = (float*)d_out;

    zconv<<<dim3(256, 8), 256>>>(z);
    cudaFuncSetAttribute(lp_mma, cudaFuncAttributeMaxDynamicSharedMemorySize,
                         SMEM_TOTAL);
    lp_mma<<<GRID, THREADS, SMEM_TOTAL>>>(W1, b1, W2, b2, out);
}

// round 10
// speedup vs baseline: 1.0058x; 1.0058x over previous
#include <cuda_runtime.h>
#include <cuda_bf16.h>
#include <cstdint>

#define THREADS 512
#define NTILES  4096
#define GRID    148

// ---- smem layout (bytes) ----
#define OFF_RING 0u          // 2 x 32768 : per chunk [hi 16K][lo 16K], A[128m][64k]
#define OFF_PS   32768u      // aliases ring buf1: 2 x 16384 fp32 [32n][128m]
#define OFF_W1   65536u      // hi 64K + lo 64K : [128 d][256 k], 512B rows
#define OFF_W2   196608u     // hi 8K + lo 8K   : [32 n][128 k], 256B rows
#define OFF_B1   212992u
#define OFF_B2   213504u
#define SMEM_TOTAL 213632u

// bf16 z in [b][y][x][ch] layout (channel-contiguous), hi and lo parts
static __device__ __align__(16) __nv_bfloat16 g_zh[8 * 256 * 256 * 32];
static __device__ __align__(16) __nv_bfloat16 g_zl[8 * 256 * 256 * 32];

__device__ __forceinline__ uint32_t smem_u32(const void* p) {
    uint32_t a;
    asm("{ .reg .u64 t; cvta.to.shared.u64 t, %1; cvt.u32.u64 %0, t; }"
        : "=r"(a) : "l"(p));
    return a;
}
__device__ __forceinline__ void ldsm4(uint32_t r[4], uint32_t addr) {
    asm volatile("ldmatrix.sync.aligned.m8n8.x4.shared.b16 {%0,%1,%2,%3}, [%4];"
                 : "=r"(r[0]), "=r"(r[1]), "=r"(r[2]), "=r"(r[3]) : "r"(addr));
}
__device__ __forceinline__ void mma16816(float c[4], const uint32_t a[4],
                                         uint32_t b0, uint32_t b1) {
    asm volatile("mma.sync.aligned.m16n8k16.row.col.f32.bf16.bf16.f32 "
                 "{%0,%1,%2,%3}, {%4,%5,%6,%7}, {%8,%9}, {%0,%1,%2,%3};"
                 : "+f"(c[0]), "+f"(c[1]), "+f"(c[2]), "+f"(c[3])
                 : "r"(a[0]), "r"(a[1]), "r"(a[2]), "r"(a[3]), "r"(b0), "r"(b1));
}
__device__ __forceinline__ uint32_t packsplit(float h0, float h1, uint32_t& lo) {
    __nv_bfloat162 th = __floats2bfloat162_rn(h0, h1);
    __nv_bfloat162 tl = __floats2bfloat162_rn(h0 - __bfloat162float(th.x),
                                              h1 - __bfloat162float(th.y));
    lo = *(uint32_t*)&tl;
    return *(uint32_t*)&th;
}
// chunk A swizzle: row stride 128B (64 bf16), 8 granules XOR row&7
__device__ __forceinline__ uint32_t swzA(int m, int k) {
    return (uint32_t)(m * 128 + (((k >> 3) ^ (m & 7)) << 4) + (k & 7) * 2);
}
__device__ __forceinline__ uint32_t swzW1(int d, int k) {   // 512B rows
    return (uint32_t)(d * 512 + (((k >> 3) ^ (d & 7)) << 4) + (k & 7) * 2);
}
__device__ __forceinline__ uint32_t swzW2(int r, int k) {   // 256B rows
    return (uint32_t)(r * 256 + (((k >> 3) ^ (r & 7)) << 4) + (k & 7) * 2);
}

// ---------------- pre-pass: fp32 z -> split bf16, channel-contiguous ----------------
__global__ __launch_bounds__(256)
void zconv(const float* __restrict__ z) {
    const int y = blockIdx.x, b = blockIdx.y, x = threadIdx.x;
    const float* src = z + (((size_t)b * 32) * 256 + y) * 256 + x;
    float v[32];
    #pragma unroll
    for (int ch = 0; ch < 32; ++ch) v[ch] = src[(size_t)ch * 65536];
    uint32_t hi[16], lo[16];
    #pragma unroll
    for (int i = 0; i < 16; ++i) hi[i] = packsplit(v[2 * i], v[2 * i + 1], lo[i]);
    size_t o = (((size_t)b * 256 + y) * 256 + x) * 32;
    uint4* dh = (uint4*)(g_zh + o);
    uint4* dl = (uint4*)(g_zl + o);
    #pragma unroll
    for (int i = 0; i < 4; ++i) {
        dh[i] = make_uint4(hi[4*i], hi[4*i+1], hi[4*i+2], hi[4*i+3]);
        dl[i] = make_uint4(lo[4*i], lo[4*i+1], lo[4*i+2], lo[4*i+3]);
    }
}

// ---------------- main kernel ----------------
__global__ __launch_bounds__(THREADS, 1)
void lp_mma(const float* __restrict__ W1, const float* __restrict__ b1,
            const float* __restrict__ W2, const float* __restrict__ b2,
            float* __restrict__ out)
{
    extern __shared__ __align__(16) char smem[];
    const uint32_t sb = smem_u32(smem);
    const int tid  = threadIdx.x;
    const int w    = tid >> 5;
    const int lane = tid & 31;

    // ---------- one-time weight staging ----------
    for (int idx = tid; idx < 128 * 256; idx += THREADS) {
        int d = idx >> 8, k = idx & 255;
        int q = k >> 5, ch = k & 31;
        int p = q + (q >= 4);                 // skip center tap
        float v = W1[d * 288 + ch * 9 + p];
        uint32_t lo, hi = packsplit(v, 0.0f, lo);
        uint32_t off = swzW1(d, k);
        *(__nv_bfloat16*)(smem + OFF_W1 + off)          = *(__nv_bfloat16*)&hi;
        *(__nv_bfloat16*)(smem + OFF_W1 + 65536u + off) = *(__nv_bfloat16*)&lo;
    }
    for (int idx = tid; idx < 32 * 128; idx += THREADS) {
        int n = idx >> 7, k = idx & 127;
        float v = W2[n * 128 + k];
        uint32_t lo, hi = packsplit(v, 0.0f, lo);
        uint32_t off = swzW2(n, k);
        *(__nv_bfloat16*)(smem + OFF_W2 + off)         = *(__nv_bfloat16*)&hi;
        *(__nv_bfloat16*)(smem + OFF_W2 + 8192u + off) = *(__nv_bfloat16*)&lo;
    }
    if (tid < 128) ((float*)(smem + OFF_B1))[tid] = b1[tid];
    if (tid < 32)  ((float*)(smem + OFF_B2))[tid] = b2[tid];
    __syncthreads();

    // ---------- warp tiling / lane addressing ----------
    const int mw = w & 7;                 // M slice (16 rows)
    const int nw = w >> 3;                // N slice (64 cols)
    const int arow  = lane & 15;
    const int kselA = lane >> 4;
    const int brow  = ((lane >> 4) << 3) + (lane & 7);
    const int kselB = (lane >> 3) & 1;
    const int xorA  = arow & 7;           // (mw*16 + arow) & 7 == arow & 7
    const int xorB  = brow & 7;

    const uint32_t rowA1 = (uint32_t)((mw * 16 + arow) * 128);
    uint32_t rowB1[4];
    #pragma unroll
    for (int jq = 0; jq < 4; ++jq)
        rowB1[jq] = (uint32_t)((nw * 64 + jq * 16 + brow) * 512);
    uint32_t rowB2[2] = { (uint32_t)(brow * 256), (uint32_t)((16 + brow) * 256) };

    // staging: thread -> (pixel, k-quarter of 16)
    const int spx = tid & 127;
    const int sq  = tid >> 7;             // 0..3
    // swizzled STS offsets for k = sq*16 (two 16B granules), fixed per thread
    const uint32_t sts0 = (uint32_t)(spx * 128 + (((2 * sq)     ^ (spx & 7)) << 4));
    const uint32_t sts1 = (uint32_t)(spx * 128 + (((2 * sq + 1) ^ (spx & 7)) << 4));

    const float* b1s = (const float*)(smem + OFF_B1);
    const float* b2s = (const float*)(smem + OFF_B2);

    uint4 ph[2], pl[2];
    auto ldg_chunk = [&](int t, int c) {
        int x0 = (t & 1) * 128, y = (t >> 1) & 255, b = t >> 9;
        int q   = sq >> 1;                   // tap within chunk
        int ch0 = (sq & 1) * 16;
        int pt  = 2 * c + q;
        int p   = pt + (pt >= 4);            // skip center tap
        int di  = p / 3, dj = p - di * 3;
        int yy  = y + di - 1, xx = x0 + spx + dj - 1;
        if ((t < NTILES) && ((unsigned)yy < 256u) && ((unsigned)xx < 256u)) {
            size_t o = ((((size_t)b * 256 + yy) * 256 + xx) * 32 + ch0);
            ph[0] = *(const uint4*)(g_zh + o);
            ph[1] = *(const uint4*)(g_zh + o + 8);
            pl[0] = *(const uint4*)(g_zl + o);
            pl[1] = *(const uint4*)(g_zl + o + 8);
        } else {
            ph[0] = ph[1] = pl[0] = pl[1] = make_uint4(0, 0, 0, 0);
        }
    };
    auto sts_chunk = [&](int buf) {
        char* base = smem + OFF_RING + (uint32_t)buf * 32768u;
        *(uint4*)(base + sts0)           = ph[0];
        *(uint4*)(base + sts1)           = ph[1];
        *(uint4*)(base + 16384u + sts0)  = pl[0];
        *(uint4*)(base + 16384u + sts1)  = pl[1];
    };

    ldg_chunk(blockIdx.x, 0);     // prologue prefetch

    for (int t = blockIdx.x; t < NTILES; t += GRID) {
        const int x0 = (t & 1) * 128;
        const int y  = (t >> 1) & 255;
        const int b  = t >> 9;

        float C[8][4];
        #pragma unroll
        for (int jo = 0; jo < 8; ++jo)
            #pragma unroll
            for (int r = 0; r < 4; ++r) C[jo][r] = 0.0f;

        // ============ layer 1: 4 chunks of K=64, register-relay ring ============
        #pragma unroll 1
        for (int c = 0; c < 4; ++c) {
            sts_chunk(c & 1);
            if (c < 3) ldg_chunk(t, c + 1);
            else       ldg_chunk(t + GRID, 0);
            __syncthreads();

            const uint32_t Ab = sb + OFF_RING + (uint32_t)((c & 1) * 32768);
            const uint32_t Bh = sb + OFF_W1;
            const uint32_t Bl = sb + OFF_W1 + 65536u;
            #pragma unroll
            for (int s = 0; s < 4; ++s) {
                const uint32_t koA = (uint32_t)(((2 * s + kselA) ^ xorA) << 4);
                const uint32_t koB = (uint32_t)(((c * 8 + 2 * s + kselB) ^ xorB) << 4);
                uint32_t ah[4], al[4], bfr[4][4];
                ldsm4(ah, Ab + rowA1 + koA);
                #pragma unroll
                for (int jq = 0; jq < 4; ++jq) ldsm4(bfr[jq], Bh + rowB1[jq] + koB);
                #pragma unroll
                for (int jo = 0; jo < 8; ++jo)
                    mma16816(C[jo], ah,
                             bfr[jo >> 1][(jo & 1) * 2], bfr[jo >> 1][(jo & 1) * 2 + 1]);
                ldsm4(al, Ab + 16384u + rowA1 + koA);
                #pragma unroll
                for (int jo = 0; jo < 8; ++jo)
                    mma16816(C[jo], al,
                             bfr[jo >> 1][(jo & 1) * 2], bfr[jo >> 1][(jo & 1) * 2 + 1]);
                #pragma unroll
                for (int jq = 0; jq < 4; ++jq) ldsm4(bfr[jq], Bl + rowB1[jq] + koB);
                #pragma unroll
                for (int jo = 0; jo < 8; ++jo)
                    mma16816(C[jo], ah,
                             bfr[jo >> 1][(jo & 1) * 2], bfr[jo >> 1][(jo & 1) * 2 + 1]);
            }
        }

        // ============ epilogue 1 in registers: C -> layer-2 A fragments ============
        uint32_t a2h[4][4], a2l[4][4];
        {
            const int c2l = (lane & 3) * 2;
            #pragma unroll
            for (int kc = 0; kc < 4; ++kc) {
                int n0 = nw * 64 + kc * 16 + c2l;
                float bA = b1s[n0], bB = b1s[n0 + 1];
                float h0 = fmaxf(C[2*kc][0] + bA, 0.0f);
                float h1 = fmaxf(C[2*kc][1] + bB, 0.0f);
                float h2 = fmaxf(C[2*kc][2] + bA, 0.0f);
                float h3 = fmaxf(C[2*kc][3] + bB, 0.0f);
                a2h[kc][0] = packsplit(h0, h1, a2l[kc][0]);
                a2h[kc][1] = packsplit(h2, h3, a2l[kc][1]);
                float bC = b1s[n0 + 8], bD = b1s[n0 + 9];
                float g0 = fmaxf(C[2*kc+1][0] + bC, 0.0f);
                float g1 = fmaxf(C[2*kc+1][1] + bD, 0.0f);
                float g2 = fmaxf(C[2*kc+1][2] + bC, 0.0f);
                float g3 = fmaxf(C[2*kc+1][3] + bD, 0.0f);
                a2h[kc][2] = packsplit(g0, g1, a2l[kc][2]);
                a2h[kc][3] = packsplit(g2, g3, a2l[kc][3]);
            }
        }

        // ============ layer 2: split-K (K=64 per nw group), N=32 ============
        float C2[4][4];
        #pragma unroll
        for (int jo = 0; jo < 4; ++jo)
            #pragma unroll
            for (int r = 0; r < 4; ++r) C2[jo][r] = 0.0f;

        #pragma unroll
        for (int ps = 0; ps < 3; ++ps) {
            const uint32_t Bb = sb + OFF_W2 + (ps == 2 ? 8192u : 0u);
            #pragma unroll
            for (int kc = 0; kc < 4; ++kc) {
                const uint32_t koB = (uint32_t)(((nw * 8 + 2 * kc + kselB) ^ xorB) << 4);
                uint32_t bfr[2][4];
                #pragma unroll
                for (int jq = 0; jq < 2; ++jq) ldsm4(bfr[jq], Bb + rowB2[jq] + koB);
                const uint32_t* A = (ps == 1) ? a2l[kc] : a2h[kc];
                #pragma unroll
                for (int jo = 0; jo < 4; ++jo)
                    mma16816(C2[jo], A,
                             bfr[jo >> 1][(jo & 1) * 2], bfr[jo >> 1][(jo & 1) * 2 + 1]);
            }
        }
        __syncthreads();     // all ring reads (chunk-3 MMAs) done before PS overwrite

        // ---- split-K partials to smem (PS aliases ring buf1) ----
        {
            float* ps = (float*)(smem + OFF_PS + (uint32_t)nw * 16384u);
            const int r0 = lane >> 2, c2l = (lane & 3) * 2;
            const int m = mw * 16 + r0;
            #pragma unroll
            for (int jo = 0; jo < 4; ++jo) {
                int n = jo * 8 + c2l;
                ps[n * 128 + m]           = C2[jo][0];
                ps[(n + 1) * 128 + m]     = C2[jo][1];
                ps[n * 128 + m + 8]       = C2[jo][2];
                ps[(n + 1) * 128 + m + 8] = C2[jo][3];
            }
        }
        __syncthreads();

        // ---- reduce + bias + store (coalesced float4) ----
        {
            const int n  = tid >> 4;
            const int m0 = (tid & 15) * 8;
            const float* p0 = (const float*)(smem + OFF_PS) + n * 128 + m0;
            const float* p1 = (const float*)(smem + OFF_PS + 16384u) + n * 128 + m0;
            const float bz = b2s[n];
            float* po = out + ((size_t)(b * 32 + n)) * 65536 + y * 256 + x0 + m0;
            #pragma unroll
            for (int i = 0; i < 2; ++i) {
                float4 u = ((const float4*)p0)[i];
                float4 v = ((const float4*)p1)[i];
                ((float4*)po)[i] = make_float4(u.x + v.x + bz, u.y + v.y + bz,
                                               u.z + v.z + bz, u.w + v.w + bz);
            }
        }
        __syncthreads();     // PS consumed before next tile's STS into buf1
    }
}

extern "C" void kernel_launch(void* const* d_in, const int* in_sizes, int n_in,
                              void* d_out, int out_size) {
    const float* z  = (const float*)d_in[0];
    const float* W1 = (const float*)d_in[1];
    const float* b1 = (const float*)d_in[2];
    const float* W2 = (const float*)d_in[3];
    const float* b2 = (const float*)d_in[4];
    float* out = (float*)d_out;

    zconv<<<dim3(256, 8), 256>>>(z);
    cudaFuncSetAttribute(lp_mma, cudaFuncAttributeMaxDynamicSharedMemorySize,
                         SMEM_TOTAL);
    lp_mma<<<GRID, THREADS, SMEM_TOTAL>>>(W1, b1, W2, b2, out);
}

// round 11
// speedup vs baseline: 2.0288x; 2.0171x over previous
#include <cuda_runtime.h>
#include <cuda_fp16.h>
#include <cstdint>

#define THREADS 512
#define NTILES  4096
#define GRID    148

// ---- smem layout (bytes) ----
#define OFF_RING 0u        // 3 x 16384 : A chunk [128 m][64 k] fp16, 128B rows
#define OFF_H    49152u    // 32768 : H [128 m][128 k] fp16, 256B rows
#define OFF_W1   81920u    // 65536 : [128 d][256 k] fp16, 512B rows
#define OFF_W2   147456u   // 8192  : [32 n][128 k] fp16, 256B rows
#define OFF_B1   155648u
#define OFF_B2   156160u
#define SMEM_TOTAL 156288u

// fp16 z in [b][y][x][ch] layout (channel-contiguous)
static __device__ __align__(16) __half g_zf[8 * 256 * 256 * 32];

__device__ __forceinline__ uint32_t smem_u32(const void* p) {
    uint32_t a;
    asm("{ .reg .u64 t; cvta.to.shared.u64 t, %1; cvt.u32.u64 %0, t; }"
        : "=r"(a) : "l"(p));
    return a;
}
__device__ __forceinline__ void ldsm4(uint32_t r[4], uint32_t addr) {
    asm volatile("ldmatrix.sync.aligned.m8n8.x4.shared.b16 {%0,%1,%2,%3}, [%4];"
                 : "=r"(r[0]), "=r"(r[1]), "=r"(r[2]), "=r"(r[3]) : "r"(addr));
}
__device__ __forceinline__ void mma16816(float c[4], const uint32_t a[4],
                                         uint32_t b0, uint32_t b1) {
    asm volatile("mma.sync.aligned.m16n8k16.row.col.f32.f16.f16.f32 "
                 "{%0,%1,%2,%3}, {%4,%5,%6,%7}, {%8,%9}, {%0,%1,%2,%3};"
                 : "+f"(c[0]), "+f"(c[1]), "+f"(c[2]), "+f"(c[3])
                 : "r"(a[0]), "r"(a[1]), "r"(a[2]), "r"(a[3]), "r"(b0), "r"(b1));
}
__device__ __forceinline__ void cp16(uint32_t dst, const void* src, bool ok) {
    asm volatile("cp.async.ca.shared.global [%0], [%1], 16, %2;"
                 :: "r"(dst), "l"(src), "r"(ok ? 16 : 0));
}
// swizzles: 16B granule index XOR (row & 7)
__device__ __forceinline__ uint32_t swzW1(int d, int k) {   // 512B rows
    return (uint32_t)(d * 512 + (((k >> 3) ^ (d & 7)) << 4) + (k & 7) * 2);
}
__device__ __forceinline__ uint32_t swzH(int r, int k) {    // 256B rows
    return (uint32_t)(r * 256 + (((k >> 3) ^ (r & 7)) << 4) + (k & 7) * 2);
}

// ---------------- pre-pass: fp32 z -> fp16, channel-contiguous ----------------
__global__ __launch_bounds__(256)
void zconv(const float* __restrict__ z) {
    const int y = blockIdx.x, b = blockIdx.y, x = threadIdx.x;
    const float* src = z + (((size_t)b * 32) * 256 + y) * 256 + x;
    float v[32];
    #pragma unroll
    for (int ch = 0; ch < 32; ++ch) v[ch] = src[(size_t)ch * 65536];
    uint32_t h[16];
    #pragma unroll
    for (int i = 0; i < 16; ++i) {
        __half2 t = __floats2half2_rn(v[2 * i], v[2 * i + 1]);
        h[i] = *(uint32_t*)&t;
    }
    uint4* d = (uint4*)(g_zf + (((size_t)b * 256 + y) * 256 + x) * 32);
    #pragma unroll
    for (int i = 0; i < 4; ++i)
        d[i] = make_uint4(h[4*i], h[4*i+1], h[4*i+2], h[4*i+3]);
}

// ---------------- main kernel ----------------
__global__ __launch_bounds__(THREADS, 1)
void lp_mma(const float* __restrict__ W1, const float* __restrict__ b1,
            const float* __restrict__ W2, const float* __restrict__ b2,
            float* __restrict__ out)
{
    extern __shared__ __align__(16) char smem[];
    const uint32_t sb = smem_u32(smem);
    const int tid  = threadIdx.x;
    const int w    = tid >> 5;
    const int lane = tid & 31;

    // ---------- one-time weight staging (fp16) ----------
    for (int idx = tid; idx < 128 * 256; idx += THREADS) {
        int d = idx >> 8, k = idx & 255;
        int q = k >> 5, ch = k & 31;
        int p = q + (q >= 4);                 // skip center tap
        *(__half*)(smem + OFF_W1 + swzW1(d, k)) = __float2half(W1[d * 288 + ch * 9 + p]);
    }
    for (int idx = tid; idx < 32 * 128; idx += THREADS) {
        int n = idx >> 7, k = idx & 127;
        *(__half*)(smem + OFF_W2 + swzH(n, k)) = __float2half(W2[n * 128 + k]);
    }
    if (tid < 128) ((float*)(smem + OFF_B1))[tid] = b1[tid];
    if (tid < 32)  ((float*)(smem + OFF_B2))[tid] = b2[tid];
    __syncthreads();

    // ---------- warp tiling / lane addressing ----------
    const int mw = w & 3;                 // layer-1 M slice (32 rows)
    const int nw = (w >> 2) & 3;          // layer-1 N slice (32 cols)
    const int arow  = lane & 15;
    const int kselA = lane >> 4;
    const int brow  = ((lane >> 4) << 3) + (lane & 7);
    const int kselB = (lane >> 3) & 1;
    const int xorA  = arow & 7;
    const int xorB  = brow & 7;

    uint32_t rowA1[2];
    #pragma unroll
    for (int mi = 0; mi < 2; ++mi)
        rowA1[mi] = (uint32_t)((mw * 32 + mi * 16 + arow) * 128);
    uint32_t rowB1[2];
    #pragma unroll
    for (int jq = 0; jq < 2; ++jq)
        rowB1[jq] = (uint32_t)((nw * 32 + jq * 16 + brow) * 512);
    // layer 2: warp pair j2 covers rows j2*16..+15; halfsel picks which 8 rows to store
    const int j2      = w >> 1;
    const int halfsel = w & 1;
    const uint32_t rowA2 = (uint32_t)((j2 * 16 + arow) * 256);
    uint32_t rowB2[2] = { (uint32_t)(brow * 256), (uint32_t)((16 + brow) * 256) };

    // staging: thread -> (pixel, k-quarter of 16)
    const int spx  = tid >> 2;
    const int sqtr = tid & 3;
    const uint32_t sg0 = (uint32_t)(spx * 128 + (((2 * sqtr)     ^ (spx & 7)) << 4));
    const uint32_t sg1 = (uint32_t)(spx * 128 + (((2 * sqtr + 1) ^ (spx & 7)) << 4));

    const float* b1s = (const float*)(smem + OFF_B1);
    const float* b2s = (const float*)(smem + OFF_B2);

    auto issue = [&](int t, int c, int buf) {
        int x0 = (t & 1) * 128, y = (t >> 1) & 255, b = t >> 9;
        int q   = sqtr >> 1;                 // tap within chunk
        int ch0 = (sqtr & 1) * 16;
        int pt  = 2 * c + q;
        int p   = pt + (pt >= 4);            // skip center tap
        int di  = p / 3, dj = p - di * 3;
        int yy  = y + di - 1, xx = x0 + spx + dj - 1;
        bool ok = (t < NTILES) && ((unsigned)yy < 256u) && ((unsigned)xx < 256u);
        size_t o = ok ? ((((size_t)b * 256 + yy) * 256 + xx) * 32 + ch0) : 0;
        const __half* src = g_zf + o;
        uint32_t base = sb + OFF_RING + (uint32_t)buf * 16384u;
        cp16(base + sg0, src, ok);
        cp16(base + sg1, src + 8, ok);
        asm volatile("cp.async.commit_group;");
    };

    issue(blockIdx.x, 0, 0);      // prologue: chunk 0 -> buf 0
    int ibuf = 1, cbuf = 0;

    for (int t = blockIdx.x; t < NTILES; t += GRID) {
        const int x0 = (t & 1) * 128;
        const int y  = (t >> 1) & 255;
        const int b  = t >> 9;

        float C[2][4][4];
        #pragma unroll
        for (int mi = 0; mi < 2; ++mi)
            #pragma unroll
            for (int jo = 0; jo < 4; ++jo)
                #pragma unroll
                for (int r = 0; r < 4; ++r) C[mi][jo][r] = 0.0f;

        // ============ layer 1: 4 chunks of K=64, 3-deep cp.async ring ============
        #pragma unroll 1
        for (int c = 0; c < 4; ++c) {
            if (c < 3) issue(t, c + 1, ibuf);
            else       issue(t + GRID, 0, ibuf);
            ibuf = (ibuf + 1) % 3;
            asm volatile("cp.async.wait_group 1;");
            __syncthreads();

            const uint32_t Ab = sb + OFF_RING + (uint32_t)cbuf * 16384u;
            cbuf = (cbuf + 1) % 3;
            #pragma unroll
            for (int s = 0; s < 4; ++s) {
                const uint32_t koA = (uint32_t)(((2 * s + kselA) ^ xorA) << 4);
                const uint32_t koB = (uint32_t)(((c * 8 + 2 * s + kselB) ^ xorB) << 4);
                uint32_t ah[2][4], bfr[2][4];
                #pragma unroll
                for (int mi = 0; mi < 2; ++mi) ldsm4(ah[mi], Ab + rowA1[mi] + koA);
                #pragma unroll
                for (int jq = 0; jq < 2; ++jq)
                    ldsm4(bfr[jq], sb + OFF_W1 + rowB1[jq] + koB);
                #pragma unroll
                for (int mi = 0; mi < 2; ++mi)
                    #pragma unroll
                    for (int jo = 0; jo < 4; ++jo)
                        mma16816(C[mi][jo], ah[mi],
                                 bfr[jo >> 1][(jo & 1) * 2], bfr[jo >> 1][(jo & 1) * 2 + 1]);
            }
        }

        // ---- epilogue 1: bias + ReLU -> fp16 H in smem ----
        {
            const int c2l = (lane & 3) * 2;
            #pragma unroll
            for (int mi = 0; mi < 2; ++mi) {
                int row0 = mw * 32 + mi * 16 + (lane >> 2);
                #pragma unroll
                for (int jo = 0; jo < 4; ++jo) {
                    int n = nw * 32 + jo * 8 + c2l;
                    float bA = b1s[n], bB = b1s[n + 1];
                    __half2 u = __floats2half2_rn(fmaxf(C[mi][jo][0] + bA, 0.0f),
                                                  fmaxf(C[mi][jo][1] + bB, 0.0f));
                    __half2 v = __floats2half2_rn(fmaxf(C[mi][jo][2] + bA, 0.0f),
                                                  fmaxf(C[mi][jo][3] + bB, 0.0f));
                    *(uint32_t*)(smem + OFF_H + swzH(row0, n))     = *(uint32_t*)&u;
                    *(uint32_t*)(smem + OFF_H + swzH(row0 + 8, n)) = *(uint32_t*)&v;
                }
            }
        }
        __syncthreads();

        // ---- load layer-2 A fragments from H ----
        uint32_t a2[8][4];
        #pragma unroll
        for (int s = 0; s < 8; ++s)
            ldsm4(a2[s], sb + OFF_H + rowA2 + (uint32_t)(((2 * s + kselA) ^ xorA) << 4));

        // ============ layer 2: m16 per warp pair, N=32, K=128 ============
        float C2[4][4];
        #pragma unroll
        for (int jo = 0; jo < 4; ++jo)
            #pragma unroll
            for (int r = 0; r < 4; ++r) C2[jo][r] = 0.0f;

        #pragma unroll
        for (int s = 0; s < 8; ++s) {
            const uint32_t koB = (uint32_t)(((2 * s + kselB) ^ xorB) << 4);
            uint32_t bfr[2][4];
            #pragma unroll
            for (int jq = 0; jq < 2; ++jq)
                ldsm4(bfr[jq], sb + OFF_W2 + rowB2[jq] + koB);
            #pragma unroll
            for (int jo = 0; jo < 4; ++jo)
                mma16816(C2[jo], a2[s],
                         bfr[jo >> 1][(jo & 1) * 2], bfr[jo >> 1][(jo & 1) * 2 + 1]);
        }

        // ---- epilogue 2: bias + store (each warp stores its 8 rows) ----
        {
            const int m = j2 * 16 + (lane >> 2) + halfsel * 8;
            const int r0 = halfsel * 2;
            #pragma unroll
            for (int jo = 0; jo < 4; ++jo) {
                int n = jo * 8 + (lane & 3) * 2;
                float* po = out + ((size_t)(b * 32 + n)) * 65536 + y * 256 + x0 + m;
                po[0]     = C2[jo][r0]     + b2s[n];
                po[65536] = C2[jo][r0 + 1] + b2s[n + 1];
            }
        }
    }
}

extern "C" void kernel_launch(void* const* d_in, const int* in_sizes, int n_in,
                              void* d_out, int out_size) {
    const float* z  = (const float*)d_in[0];
    const float* W1 = (const float*)d_in[1];
    const float* b1 = (const float*)d_in[2];
    const float* W2 = (const float*)d_in[3];
    const float* b2 = (const float*)d_in[4];
    float* out = (float*)d_out;

    zconv<<<dim3(256, 8), 256>>>(z);
    cudaFuncSetAttribute(lp_mma, cudaFuncAttributeMaxDynamicSharedMemorySize,
                         SMEM_TOTAL);
    lp_mma<<<GRID, THREADS, SMEM_TOTAL>>>(W1, b1, W2, b2, out);
}

// round 12
// speedup vs baseline: 2.1439x; 1.0567x over previous
#include <cuda_runtime.h>
#include <cuda_fp16.h>
#include <cstdint>

#define THREADS 256
#define NTILES  4096
#define GRID    148

// ---- smem layout (bytes) ----
#define OFF_RING 0u        // 3 x 16384 : A chunk [128 m][64 k] fp16, 128B rows
#define OFF_H    49152u    // 32768 : H [128 m][128 k] fp16, 256B rows
#define OFF_W1   81920u    // 65536 : [128 d][256 k] fp16, 512B rows
#define OFF_W2   147456u   // 8192  : [32 n][128 k] fp16, 256B rows
#define OFF_B1   155648u
#define OFF_B2   156160u
#define SMEM_TOTAL 156288u

// fp16 z in [b][y][x][ch] layout (channel-contiguous)
static __device__ __align__(16) __half g_zf[8 * 256 * 256 * 32];

__device__ __forceinline__ uint32_t smem_u32(const void* p) {
    uint32_t a;
    asm("{ .reg .u64 t; cvta.to.shared.u64 t, %1; cvt.u32.u64 %0, t; }"
        : "=r"(a) : "l"(p));
    return a;
}
__device__ __forceinline__ void ldsm4(uint32_t r[4], uint32_t addr) {
    asm volatile("ldmatrix.sync.aligned.m8n8.x4.shared.b16 {%0,%1,%2,%3}, [%4];"
                 : "=r"(r[0]), "=r"(r[1]), "=r"(r[2]), "=r"(r[3]) : "r"(addr));
}
__device__ __forceinline__ void mma16816(float c[4], const uint32_t a[4],
                                         uint32_t b0, uint32_t b1) {
    asm volatile("mma.sync.aligned.m16n8k16.row.col.f32.f16.f16.f32 "
                 "{%0,%1,%2,%3}, {%4,%5,%6,%7}, {%8,%9}, {%0,%1,%2,%3};"
                 : "+f"(c[0]), "+f"(c[1]), "+f"(c[2]), "+f"(c[3])
                 : "r"(a[0]), "r"(a[1]), "r"(a[2]), "r"(a[3]), "r"(b0), "r"(b1));
}
__device__ __forceinline__ void cp16(uint32_t dst, const void* src, bool ok) {
    asm volatile("cp.async.ca.shared.global [%0], [%1], 16, %2;"
                 :: "r"(dst), "l"(src), "r"(ok ? 16 : 0));
}
// swizzles: 16B granule index XOR (row & 7)
__device__ __forceinline__ uint32_t swzW1(int d, int k) {   // 512B rows
    return (uint32_t)(d * 512 + (((k >> 3) ^ (d & 7)) << 4) + (k & 7) * 2);
}
__device__ __forceinline__ uint32_t swzH(int r, int k) {    // 256B rows
    return (uint32_t)(r * 256 + (((k >> 3) ^ (r & 7)) << 4) + (k & 7) * 2);
}

// ---------------- pre-pass: fp32 z -> fp16, channel-contiguous ----------------
__global__ __launch_bounds__(256)
void zconv(const float* __restrict__ z) {
    const int y = blockIdx.x, b = blockIdx.y, x = threadIdx.x;
    const float* src = z + (((size_t)b * 32) * 256 + y) * 256 + x;
    float v[32];
    #pragma unroll
    for (int ch = 0; ch < 32; ++ch) v[ch] = src[(size_t)ch * 65536];
    uint32_t h[16];
    #pragma unroll
    for (int i = 0; i < 16; ++i) {
        __half2 t = __floats2half2_rn(v[2 * i], v[2 * i + 1]);
        h[i] = *(uint32_t*)&t;
    }
    uint4* d = (uint4*)(g_zf + (((size_t)b * 256 + y) * 256 + x) * 32);
    #pragma unroll
    for (int i = 0; i < 4; ++i)
        d[i] = make_uint4(h[4*i], h[4*i+1], h[4*i+2], h[4*i+3]);
}

// ---------------- main kernel ----------------
__global__ __launch_bounds__(THREADS, 1)
void lp_mma(const float* __restrict__ W1, const float* __restrict__ b1,
            const float* __restrict__ W2, const float* __restrict__ b2,
            float* __restrict__ out)
{
    extern __shared__ __align__(16) char smem[];
    const uint32_t sb = smem_u32(smem);
    const int tid  = threadIdx.x;
    const int w    = tid >> 5;
    const int lane = tid & 31;

    // ---------- one-time weight staging (fp16) ----------
    for (int idx = tid; idx < 128 * 256; idx += THREADS) {
        int d = idx >> 8, k = idx & 255;
        int q = k >> 5, ch = k & 31;
        int p = q + (q >= 4);                 // skip center tap
        *(__half*)(smem + OFF_W1 + swzW1(d, k)) = __float2half(W1[d * 288 + ch * 9 + p]);
    }
    for (int idx = tid; idx < 32 * 128; idx += THREADS) {
        int n = idx >> 7, k = idx & 127;
        *(__half*)(smem + OFF_W2 + swzH(n, k)) = __float2half(W2[n * 128 + k]);
    }
    if (tid < 128) ((float*)(smem + OFF_B1))[tid] = b1[tid];
    if (tid < 32)  ((float*)(smem + OFF_B2))[tid] = b2[tid];
    __syncthreads();

    // ---------- warp tiling / lane addressing ----------
    const int mw = w & 3;                 // layer-1 M slice (32 rows)
    const int nw = w >> 2;                // layer-1 N slice (64 cols)
    const int arow  = lane & 15;
    const int kselA = lane >> 4;
    const int brow  = ((lane >> 4) << 3) + (lane & 7);
    const int kselB = (lane >> 3) & 1;
    const int xorA  = arow & 7;
    const int xorB  = brow & 7;

    uint32_t rowA1[2];
    #pragma unroll
    for (int mi = 0; mi < 2; ++mi)
        rowA1[mi] = (uint32_t)((mw * 32 + mi * 16 + arow) * 128);
    uint32_t rowB1[4];
    #pragma unroll
    for (int jq = 0; jq < 4; ++jq)
        rowB1[jq] = (uint32_t)((nw * 64 + jq * 16 + brow) * 512);
    // layer 2: warp w covers rows w*16..+15
    const uint32_t rowA2 = (uint32_t)((w * 16 + arow) * 256);
    uint32_t rowB2[2] = { (uint32_t)(brow * 256), (uint32_t)((16 + brow) * 256) };

    // staging: thread -> (pixel, tap); 32 ch = 64B contiguous = 4 x cp16
    const int spx = tid >> 1;
    const int sq  = tid & 1;
    uint32_t sg[4];
    #pragma unroll
    for (int i = 0; i < 4; ++i)
        sg[i] = (uint32_t)(spx * 128 + (((sq * 4 + i) ^ (spx & 7)) << 4));

    const float* b1s = (const float*)(smem + OFF_B1);
    const float* b2s = (const float*)(smem + OFF_B2);

    auto issue = [&](int t, int c, int buf) {
        int x0 = (t & 1) * 128, y = (t >> 1) & 255, b = t >> 9;
        int pt  = 2 * c + sq;
        int p   = pt + (pt >= 4);            // skip center tap
        int di  = p / 3, dj = p - di * 3;
        int yy  = y + di - 1, xx = x0 + spx + dj - 1;
        bool ok = (t < NTILES) && ((unsigned)yy < 256u) && ((unsigned)xx < 256u);
        size_t o = ok ? ((((size_t)b * 256 + yy) * 256 + xx) * 32) : 0;
        const __half* src = g_zf + o;
        uint32_t base = sb + OFF_RING + (uint32_t)buf * 16384u;
        #pragma unroll
        for (int i = 0; i < 4; ++i) cp16(base + sg[i], src + i * 8, ok);
        asm volatile("cp.async.commit_group;");
    };

    issue(blockIdx.x, 0, 0);      // prologue: chunk 0 -> buf 0
    int ibuf = 1, cbuf = 0;

    for (int t = blockIdx.x; t < NTILES; t += GRID) {
        const int x0 = (t & 1) * 128;
        const int y  = (t >> 1) & 255;
        const int b  = t >> 9;

        float C[2][8][4];
        #pragma unroll
        for (int mi = 0; mi < 2; ++mi)
            #pragma unroll
            for (int jo = 0; jo < 8; ++jo)
                #pragma unroll
                for (int r = 0; r < 4; ++r) C[mi][jo][r] = 0.0f;

        // ============ layer 1: 4 chunks of K=64, 3-deep cp.async ring ============
        #pragma unroll 1
        for (int c = 0; c < 4; ++c) {
            if (c < 3) issue(t, c + 1, ibuf);
            else       issue(t + GRID, 0, ibuf);
            ibuf = (ibuf + 1) % 3;
            asm volatile("cp.async.wait_group 1;");
            __syncthreads();

            const uint32_t Ab = sb + OFF_RING + (uint32_t)cbuf * 16384u;
            cbuf = (cbuf + 1) % 3;
            #pragma unroll
            for (int s = 0; s < 4; ++s) {
                const uint32_t koA = (uint32_t)(((2 * s + kselA) ^ xorA) << 4);
                const uint32_t koB = (uint32_t)(((c * 8 + 2 * s + kselB) ^ xorB) << 4);
                uint32_t ah[2][4], bfr[4][4];
                #pragma unroll
                for (int mi = 0; mi < 2; ++mi) ldsm4(ah[mi], Ab + rowA1[mi] + koA);
                #pragma unroll
                for (int jq = 0; jq < 4; ++jq)
                    ldsm4(bfr[jq], sb + OFF_W1 + rowB1[jq] + koB);
                #pragma unroll
                for (int mi = 0; mi < 2; ++mi)
                    #pragma unroll
                    for (int jo = 0; jo < 8; ++jo)
                        mma16816(C[mi][jo], ah[mi],
                                 bfr[jo >> 1][(jo & 1) * 2], bfr[jo >> 1][(jo & 1) * 2 + 1]);
            }
        }

        // ---- epilogue 1: bias + ReLU -> fp16 H in smem ----
        {
            const int c2l = (lane & 3) * 2;
            #pragma unroll
            for (int mi = 0; mi < 2; ++mi) {
                int row0 = mw * 32 + mi * 16 + (lane >> 2);
                #pragma unroll
                for (int jo = 0; jo < 8; ++jo) {
                    int n = nw * 64 + jo * 8 + c2l;
                    float bA = b1s[n], bB = b1s[n + 1];
                    __half2 u = __floats2half2_rn(fmaxf(C[mi][jo][0] + bA, 0.0f),
                                                  fmaxf(C[mi][jo][1] + bB, 0.0f));
                    __half2 v = __floats2half2_rn(fmaxf(C[mi][jo][2] + bA, 0.0f),
                                                  fmaxf(C[mi][jo][3] + bB, 0.0f));
                    *(uint32_t*)(smem + OFF_H + swzH(row0, n))     = *(uint32_t*)&u;
                    *(uint32_t*)(smem + OFF_H + swzH(row0 + 8, n)) = *(uint32_t*)&v;
                }
            }
        }
        __syncthreads();

        // ---- load layer-2 A fragments from H ----
        uint32_t a2[8][4];
        #pragma unroll
        for (int s = 0; s < 8; ++s)
            ldsm4(a2[s], sb + OFF_H + rowA2 + (uint32_t)(((2 * s + kselA) ^ xorA) << 4));

        // ============ layer 2: m16 per warp, N=32, K=128 ============
        float C2[4][4];
        #pragma unroll
        for (int jo = 0; jo < 4; ++jo)
            #pragma unroll
            for (int r = 0; r < 4; ++r) C2[jo][r] = 0.0f;

        #pragma unroll
        for (int s = 0; s < 8; ++s) {
            const uint32_t koB = (uint32_t)(((2 * s + kselB) ^ xorB) << 4);
            uint32_t bfr[2][4];
            #pragma unroll
            for (int jq = 0; jq < 2; ++jq)
                ldsm4(bfr[jq], sb + OFF_W2 + rowB2[jq] + koB);
            #pragma unroll
            for (int jo = 0; jo < 4; ++jo)
                mma16816(C2[jo], a2[s],
                         bfr[jo >> 1][(jo & 1) * 2], bfr[jo >> 1][(jo & 1) * 2 + 1]);
        }

        // ---- epilogue 2: bias + store (warp stores its full m16) ----
        {
            const int m = w * 16 + (lane >> 2);
            #pragma unroll
            for (int jo = 0; jo < 4; ++jo) {
                int n = jo * 8 + (lane & 3) * 2;
                float* po = out + ((size_t)(b * 32 + n)) * 65536 + y * 256 + x0 + m;
                po[0]         = C2[jo][0] + b2s[n];
                po[65536]     = C2[jo][1] + b2s[n + 1];
                po[8]         = C2[jo][2] + b2s[n];
                po[8 + 65536] = C2[jo][3] + b2s[n + 1];
            }
        }
    }
}

extern "C" void kernel_launch(void* const* d_in, const int* in_sizes, int n_in,
                              void* d_out, int out_size) {
    const float* z  = (const float*)d_in[0];
    const float* W1 = (const float*)d_in[1];
    const float* b1 = (const float*)d_in[2];
    const float* W2 = (const float*)d_in[3];
    const float* b2 = (const float*)d_in[4];
    float* out = (float*)d_out;

    zconv<<<dim3(256, 8), 256>>>(z);
    cudaFuncSetAttribute(lp_mma, cudaFuncAttributeMaxDynamicSharedMemorySize,
                         SMEM_TOTAL);
    lp_mma<<<GRID, THREADS, SMEM_TOTAL>>>(W1, b1, W2, b2, out);
}

// round 13
// speedup vs baseline: 2.5492x; 1.1890x over previous
#include <cuda_runtime.h>
#include <cuda_fp16.h>
#include <cstdint>

#define THREADS 512
#define NTILES  4096
#define GRID    148
#define STRIDE  (2 * GRID)

// ---- smem layout (bytes) ----
#define OFF_RING 0u        // 2 groups x 3 bufs x 8192 : A chunk [128 m][32 k] fp16, 64B rows
#define OFF_H    49152u    // 2 groups x 32768 : H [128 m][128 k] fp16, 256B rows
#define OFF_W1   114688u   // 65536 : [128 d][256 k] fp16, 512B rows
#define OFF_W2   180224u   // 8192  : [32 n][128 k] fp16, 256B rows
#define OFF_B1   188416u
#define OFF_B2   188928u
#define SMEM_TOTAL 189056u

// fp16 z in [b][y][x][ch] layout (channel-contiguous)
static __device__ __align__(16) __half g_zf[8 * 256 * 256 * 32];

__device__ __forceinline__ uint32_t smem_u32(const void* p) {
    uint32_t a;
    asm("{ .reg .u64 t; cvta.to.shared.u64 t, %1; cvt.u32.u64 %0, t; }"
        : "=r"(a) : "l"(p));
    return a;
}
__device__ __forceinline__ void ldsm4(uint32_t r[4], uint32_t addr) {
    asm volatile("ldmatrix.sync.aligned.m8n8.x4.shared.b16 {%0,%1,%2,%3}, [%4];"
                 : "=r"(r[0]), "=r"(r[1]), "=r"(r[2]), "=r"(r[3]) : "r"(addr));
}
__device__ __forceinline__ void mma16816(float c[4], const uint32_t a[4],
                                         uint32_t b0, uint32_t b1) {
    asm volatile("mma.sync.aligned.m16n8k16.row.col.f32.f16.f16.f32 "
                 "{%0,%1,%2,%3}, {%4,%5,%6,%7}, {%8,%9}, {%0,%1,%2,%3};"
                 : "+f"(c[0]), "+f"(c[1]), "+f"(c[2]), "+f"(c[3])
                 : "r"(a[0]), "r"(a[1]), "r"(a[2]), "r"(a[3]), "r"(b0), "r"(b1));
}
__device__ __forceinline__ void cp16(uint32_t dst, const void* src, bool ok) {
    asm volatile("cp.async.ca.shared.global [%0], [%1], 16, %2;"
                 :: "r"(dst), "l"(src), "r"(ok ? 16 : 0));
}
#define GBAR(g) asm volatile("bar.sync %0, 256;" :: "r"((g) + 1) : "memory")

// swizzles
__device__ __forceinline__ uint32_t swzW1(int d, int k) {   // 512B rows
    return (uint32_t)(d * 512 + (((k >> 3) ^ (d & 7)) << 4) + (k & 7) * 2);
}
__device__ __forceinline__ uint32_t swzH(int r, int k) {    // 256B rows
    return (uint32_t)(r * 256 + (((k >> 3) ^ (r & 7)) << 4) + (k & 7) * 2);
}

// ---------------- pre-pass: fp32 z -> fp16, channel-contiguous ----------------
__global__ __launch_bounds__(256)
void zconv(const float* __restrict__ z) {
    const int y = blockIdx.x, b = blockIdx.y, x = threadIdx.x;
    const float* src = z + (((size_t)b * 32) * 256 + y) * 256 + x;
    float v[32];
    #pragma unroll
    for (int ch = 0; ch < 32; ++ch) v[ch] = src[(size_t)ch * 65536];
    uint32_t h[16];
    #pragma unroll
    for (int i = 0; i < 16; ++i) {
        __half2 t = __floats2half2_rn(v[2 * i], v[2 * i + 1]);
        h[i] = *(uint32_t*)&t;
    }
    uint4* d = (uint4*)(g_zf + (((size_t)b * 256 + y) * 256 + x) * 32);
    #pragma unroll
    for (int i = 0; i < 4; ++i)
        d[i] = make_uint4(h[4*i], h[4*i+1], h[4*i+2], h[4*i+3]);
}

// ---------------- main kernel: 2 independent 8-warp groups ----------------
__global__ __launch_bounds__(THREADS, 1)
void lp_mma(const float* __restrict__ W1, const float* __restrict__ b1,
            const float* __restrict__ W2, const float* __restrict__ b2,
            float* __restrict__ out)
{
    extern __shared__ __align__(16) char smem[];
    const uint32_t sb = smem_u32(smem);
    const int tid  = threadIdx.x;
    const int g    = tid >> 8;            // group 0/1
    const int gtid = tid & 255;
    const int w    = gtid >> 5;           // warp within group 0..7
    const int lane = tid & 31;

    // ---------- one-time weight staging (all 512 threads) ----------
    for (int idx = tid; idx < 128 * 256; idx += THREADS) {
        int d = idx >> 8, k = idx & 255;
        int q = k >> 5, ch = k & 31;
        int p = q + (q >= 4);                 // skip center tap
        *(__half*)(smem + OFF_W1 + swzW1(d, k)) = __float2half(W1[d * 288 + ch * 9 + p]);
    }
    for (int idx = tid; idx < 32 * 128; idx += THREADS) {
        int n = idx >> 7, k = idx & 127;
        *(__half*)(smem + OFF_W2 + swzH(n, k)) = __float2half(W2[n * 128 + k]);
    }
    if (tid < 128) ((float*)(smem + OFF_B1))[tid] = b1[tid];
    if (tid < 32)  ((float*)(smem + OFF_B2))[tid] = b2[tid];
    __syncthreads();

    // ---------- per-group bases ----------
    const uint32_t ringb = sb + OFF_RING + (uint32_t)g * 24576u;
    const uint32_t Hb    = sb + OFF_H    + (uint32_t)g * 32768u;

    // ---------- warp tiling / lane addressing ----------
    const int mw = w & 3;                 // layer-1 M slice (32 rows)
    const int nw = w >> 2;                // layer-1 N slice (64 cols)
    const int arow  = lane & 15;
    const int kselA = lane >> 4;
    const int brow  = ((lane >> 4) << 3) + (lane & 7);
    const int kselB = (lane >> 3) & 1;
    const int xorA2 = (arow >> 1) & 3;    // 64B-row A buffer granule XOR
    const int xorAH = arow & 7;           // 256B-row H granule XOR
    const int xorB  = brow & 7;

    uint32_t rowA1[2];
    #pragma unroll
    for (int mi = 0; mi < 2; ++mi)
        rowA1[mi] = (uint32_t)((mw * 32 + mi * 16 + arow) * 64);
    uint32_t rowB1[4];
    #pragma unroll
    for (int jq = 0; jq < 4; ++jq)
        rowB1[jq] = (uint32_t)((nw * 64 + jq * 16 + brow) * 512);
    const uint32_t rowA2 = (uint32_t)((w * 16 + arow) * 256);
    uint32_t rowB2[2] = { (uint32_t)(brow * 256), (uint32_t)((16 + brow) * 256) };

    // staging: group thread -> (pixel, ch-half); chunk = 1 tap x 32 ch (8KB)
    const int spx = gtid >> 1;
    const int sq  = gtid & 1;
    uint32_t sg0 = (uint32_t)(spx * 64 + (((2 * sq)     ^ ((spx >> 1) & 3)) << 4));
    uint32_t sg1 = (uint32_t)(spx * 64 + (((2 * sq + 1) ^ ((spx >> 1) & 3)) << 4));

    const float* b1s = (const float*)(smem + OFF_B1);
    const float* b2s = (const float*)(smem + OFF_B2);

    auto issue = [&](int t, int c, int buf) {
        int x0 = (t & 1) * 128, y = (t >> 1) & 255, b = t >> 9;
        int p  = c + (c >= 4);               // skip center tap
        int di = p / 3, dj = p - di * 3;
        int yy = y + di - 1, xx = x0 + spx + dj - 1;
        bool ok = (t < NTILES) && ((unsigned)yy < 256u) && ((unsigned)xx < 256u);
        size_t o = ok ? ((((size_t)b * 256 + yy) * 256 + xx) * 32 + sq * 16) : 0;
        const __half* src = g_zf + o;
        uint32_t base = ringb + (uint32_t)buf * 8192u;
        cp16(base + sg0, src, ok);
        cp16(base + sg1, src + 8, ok);
        asm volatile("cp.async.commit_group;");
    };

    int t0 = 2 * blockIdx.x + g;
    issue(t0, 0, 0);                      // prologue: chunk 0 -> buf 0
    int ibuf = 1, cbuf = 0;

    for (int t = t0; t < NTILES; t += STRIDE) {
        const int x0 = (t & 1) * 128;
        const int y  = (t >> 1) & 255;
        const int b  = t >> 9;

        float C[2][8][4];
        #pragma unroll
        for (int mi = 0; mi < 2; ++mi)
            #pragma unroll
            for (int jo = 0; jo < 8; ++jo)
                #pragma unroll
                for (int r = 0; r < 4; ++r) C[mi][jo][r] = 0.0f;

        // ============ layer 1: 8 chunks of K=32, 3-deep cp.async ring ============
        #pragma unroll 1
        for (int c = 0; c < 8; ++c) {
            if (c < 7) issue(t, c + 1, ibuf);
            else       issue(t + STRIDE, 0, ibuf);
            ibuf = (ibuf == 2) ? 0 : ibuf + 1;
            asm volatile("cp.async.wait_group 1;");
            GBAR(g);

            const uint32_t Ab = ringb + (uint32_t)cbuf * 8192u;
            cbuf = (cbuf == 2) ? 0 : cbuf + 1;
            #pragma unroll
            for (int s = 0; s < 2; ++s) {
                const uint32_t koA = (uint32_t)((((2 * s + kselA) ^ xorA2) & 3) << 4);
                const uint32_t koB = (uint32_t)(((c * 4 + 2 * s + kselB) ^ xorB) << 4);
                uint32_t ah[2][4], bfr[4][4];
                #pragma unroll
                for (int mi = 0; mi < 2; ++mi) ldsm4(ah[mi], Ab + rowA1[mi] + koA);
                #pragma unroll
                for (int jq = 0; jq < 4; ++jq)
                    ldsm4(bfr[jq], sb + OFF_W1 + rowB1[jq] + koB);
                #pragma unroll
                for (int mi = 0; mi < 2; ++mi)
                    #pragma unroll
                    for (int jo = 0; jo < 8; ++jo)
                        mma16816(C[mi][jo], ah[mi],
                                 bfr[jo >> 1][(jo & 1) * 2], bfr[jo >> 1][(jo & 1) * 2 + 1]);
            }
        }

        // ---- epilogue 1: bias + ReLU -> fp16 H (group-private) ----
        {
            const int c2l = (lane & 3) * 2;
            #pragma unroll
            for (int mi = 0; mi < 2; ++mi) {
                int row0 = mw * 32 + mi * 16 + (lane >> 2);
                #pragma unroll
                for (int jo = 0; jo < 8; ++jo) {
                    int n = nw * 64 + jo * 8 + c2l;
                    float bA = b1s[n], bB = b1s[n + 1];
                    __half2 u = __floats2half2_rn(fmaxf(C[mi][jo][0] + bA, 0.0f),
                                                  fmaxf(C[mi][jo][1] + bB, 0.0f));
                    __half2 v = __floats2half2_rn(fmaxf(C[mi][jo][2] + bA, 0.0f),
                                                  fmaxf(C[mi][jo][3] + bB, 0.0f));
                    *(uint32_t*)(smem + (Hb - sb) + swzH(row0, n))     = *(uint32_t*)&u;
                    *(uint32_t*)(smem + (Hb - sb) + swzH(row0 + 8, n)) = *(uint32_t*)&v;
                }
            }
        }
        GBAR(g);

        // ---- load layer-2 A fragments from H ----
        uint32_t a2[8][4];
        #pragma unroll
        for (int s = 0; s < 8; ++s)
            ldsm4(a2[s], Hb + rowA2 + (uint32_t)(((2 * s + kselA) ^ xorAH) << 4));

        // ============ layer 2: m16 per warp, N=32, K=128 ============
        float C2[4][4];
        #pragma unroll
        for (int jo = 0; jo < 4; ++jo)
            #pragma unroll
            for (int r = 0; r < 4; ++r) C2[jo][r] = 0.0f;

        #pragma unroll
        for (int s = 0; s < 8; ++s) {
            const uint32_t koB = (uint32_t)(((2 * s + kselB) ^ xorB) << 4);
            uint32_t bfr[2][4];
            #pragma unroll
            for (int jq = 0; jq < 2; ++jq)
                ldsm4(bfr[jq], sb + OFF_W2 + rowB2[jq] + koB);
            #pragma unroll
            for (int jo = 0; jo < 4; ++jo)
                mma16816(C2[jo], a2[s],
                         bfr[jo >> 1][(jo & 1) * 2], bfr[jo >> 1][(jo & 1) * 2 + 1]);
        }

        // ---- epilogue 2: bias + store (warp stores its m16) ----
        {
            const int m = w * 16 + (lane >> 2);
            #pragma unroll
            for (int jo = 0; jo < 4; ++jo) {
                int n = jo * 8 + (lane & 3) * 2;
                float* po = out + ((size_t)(b * 32 + n)) * 65536 + y * 256 + x0 + m;
                po[0]         = C2[jo][0] + b2s[n];
                po[65536]     = C2[jo][1] + b2s[n + 1];
                po[8]         = C2[jo][2] + b2s[n];
                po[8 + 65536] = C2[jo][3] + b2s[n + 1];
            }
        }
    }
}

extern "C" void kernel_launch(void* const* d_in, const int* in_sizes, int n_in,
                              void* d_out, int out_size) {
    const float* z  = (const float*)d_in[0];
    const float* W1 = (const float*)d_in[1];
    const float* b1 = (const float*)d_in[2];
    const float* W2 = (const float*)d_in[3];
    const float* b2 = (const float*)d_in[4];
    float* out = (float*)d_out;

    zconv<<<dim3(256, 8), 256>>>(z);
    cudaFuncSetAttribute(lp_mma, cudaFuncAttributeMaxDynamicSharedMemorySize,
                         SMEM_TOTAL);
    lp_mma<<<GRID, THREADS, SMEM_TOTAL>>>(W1, b1, W2, b2, out);
}